// round 13
// baseline (speedup 1.0000x reference)
#include <cuda_runtime.h>
#include <cuda_bf16.h>
#include <stdint.h>

// Problem constants
#define BSZ 8
#define SEQ 4096
#define HID 1024
#define NEXP 8
#define CAP 512
#define NTOK (BSZ * SEQ)           // 32768
#define NPAIR (BSZ * NEXP)         // 64
#define IDX_OFF 0
#define SCORE_OFF (NPAIR * CAP)    // 32768
#define MASK_OFF (2 * NPAIR * CAP) // 65536
#define MASK_FLOATS (NPAIR * CAP * SEQ)   // 134217728

#define GATE_BLOCKS 1024           // 8 warps x 4 tokens = 32 tokens/block
#define ZF_PER_BLK  32768          // floats per zero-fill block (128 KB)
#define ZF_BLOCKS_TOTAL (MASK_FLOATS / ZF_PER_BLK)   // 4096
#define ZF_BLOCKS_A 1344           // ~176 MB rides with the gate
#define ZF_BLOCKS_B (ZF_BLOCKS_TOTAL - ZF_BLOCKS_A)  // 2752 (~361 MB) with topk
#define ZF_A_FLOATS ((size_t)ZF_BLOCKS_A * ZF_PER_BLK)

// Scratch (device globals; no allocation allowed)
__device__ float g_aff[NPAIR * SEQ];   // affinity [b*8+e][s]
__device__ int   g_idx[NPAIR * CAP];   // chosen token per (pair, slot)

// ---------------------------------------------------------------------------
// Kernel A: gate (blocks [0,1024)) + zero-fill part 1 (blocks [1024, +1344)).
// Gate arithmetic FROZEN bit-exact since R9 (k = 4L+j+128i partition, xor
// tree, exact max, fsub.rn, libdevice expf, sequential e-sum, __fdiv_rn).
// ---------------------------------------------------------------------------
__global__ __launch_bounds__(256) void gate_zf_kernel(
    const float* __restrict__ hid, const float* __restrict__ w,
    float* __restrict__ out)
{
    __shared__ float ws[NEXP * HID];
    int tid = threadIdx.x;

    if (blockIdx.x >= GATE_BLOCKS) {
        size_t base = (size_t)MASK_OFF +
                      (size_t)(blockIdx.x - GATE_BLOCKS) * ZF_PER_BLK;
        float4* dst = (float4*)(out + base);
        float4 z = make_float4(0.f, 0.f, 0.f, 0.f);
#pragma unroll
        for (int q = tid; q < ZF_PER_BLK / 4; q += 256)
            dst[q] = z;
        return;
    }

    // ---- gate path (bit-exact, frozen) ----
    for (int i = tid; i < HID * NEXP; i += 256) {
        int k = i >> 3, e = i & 7;
        ws[e * HID + k] = w[i];
    }
    __syncthreads();

    int warp = tid >> 5, lane = tid & 31;
    int tok0 = (blockIdx.x * 8 + warp) * 4;

    float acc[4][8];
#pragma unroll
    for (int t = 0; t < 4; t++)
#pragma unroll
        for (int e = 0; e < 8; e++) acc[t][e] = 0.0f;

    const float* h0 = hid + (size_t)tok0 * HID;

#pragma unroll
    for (int i = 0; i < 8; i++) {
        int kbase = i * 128 + lane * 4;
        float wreg[8][4];
#pragma unroll
        for (int e = 0; e < 8; e++)
#pragma unroll
            for (int j = 0; j < 4; j++)
                wreg[e][j] = ws[e * HID + kbase + j];
#pragma unroll
        for (int t = 0; t < 4; t++) {
            float4 h4 = *(const float4*)(h0 + (size_t)t * HID + kbase);
            float hj[4] = {h4.x, h4.y, h4.z, h4.w};
#pragma unroll
            for (int e = 0; e < 8; e++) {
#pragma unroll
                for (int j = 0; j < 4; j++)
                    acc[t][e] = __fmaf_rn(hj[j], wreg[e][j], acc[t][e]);
            }
        }
    }

#pragma unroll
    for (int off = 16; off > 0; off >>= 1) {
#pragma unroll
        for (int t = 0; t < 4; t++)
#pragma unroll
            for (int e = 0; e < 8; e++)
                acc[t][e] = __fadd_rn(acc[t][e],
                                      __shfl_xor_sync(0xFFFFFFFFu, acc[t][e], off));
    }

    if (lane < 4) {
        int tok = tok0 + lane;
        int b = tok >> 12;
        int s = tok & (SEQ - 1);

        float m = acc[lane][0];
#pragma unroll
        for (int e = 1; e < 8; e++) m = fmaxf(m, acc[lane][e]);

        float ex[8];
        float sum = 0.0f;
#pragma unroll
        for (int e = 0; e < 8; e++) {
            float d = __fsub_rn(acc[lane][e], m);
            ex[e] = expf(d);
            sum = __fadd_rn(sum, ex[e]);
        }
#pragma unroll
        for (int e = 0; e < 8; e++)
            g_aff[((size_t)(b * NEXP + e)) * SEQ + s] = __fdiv_rn(ex[e], sum);
    }
}

// ---------------------------------------------------------------------------
// Kernel B: topk sort (blocks [0,64)) + zero-fill part 2 (blocks [64, +2752)).
// Sort blocks touch no HBM until the tiny idx/score epilogue; ZF blocks
// stream zeros on the other SMs -> both resources stay busy.
// ---------------------------------------------------------------------------
__global__ __launch_bounds__(1024) void topk_zf_kernel(float* __restrict__ out)
{
    __shared__ unsigned long long keys[SEQ];

    if (blockIdx.x >= NPAIR) {
        size_t base = (size_t)MASK_OFF + ZF_A_FLOATS +
                      (size_t)(blockIdx.x - NPAIR) * ZF_PER_BLK;
        float4* dst = (float4*)(out + base);
        float4 z = make_float4(0.f, 0.f, 0.f, 0.f);
#pragma unroll
        for (int q = threadIdx.x; q < ZF_PER_BLK / 4; q += 1024)
            dst[q] = z;
        return;
    }

    int pair = blockIdx.x;
    const float* a = g_aff + (size_t)pair * SEQ;

    for (int si = threadIdx.x; si < SEQ; si += 1024) {
        unsigned int fb = __float_as_uint(a[si]);   // softmax output > 0
        keys[si] = ((unsigned long long)fb << 32) | (unsigned int)(~si);
    }
    __syncthreads();

    for (int k = 2; k <= SEQ; k <<= 1) {
        for (int j = k >> 1; j > 0; j >>= 1) {
#pragma unroll 2
            for (int i = threadIdx.x; i < SEQ; i += 1024) {
                int ixj = i ^ j;
                if (ixj > i) {
                    unsigned long long x = keys[i], y = keys[ixj];
                    bool desc = ((i & k) == 0);
                    if (desc ? (x < y) : (x > y)) { keys[i] = y; keys[ixj] = x; }
                }
            }
            __syncthreads();
        }
    }

    int cslot = threadIdx.x;
    if (cslot < CAP) {
        unsigned long long key = keys[cslot];
        int   si = (int)(~(unsigned int)key);
        float v  = __uint_as_float((unsigned int)(key >> 32));
        int row = pair * CAP + cslot;
        out[IDX_OFF + row]   = (float)si;   // topk_indices (as float)
        out[SCORE_OFF + row] = v;           // topk_scores (SCALE=1.0)
        g_idx[row] = si;
    }
}

// ---------------------------------------------------------------------------
// Kernel C: one-hot scatter (after all zero-fill has completed).
// ---------------------------------------------------------------------------
__global__ __launch_bounds__(512) void onehot_kernel(float* __restrict__ out)
{
    int row = blockIdx.x * 512 + threadIdx.x;    // 0 .. 32767
    out[MASK_OFF + (size_t)row * SEQ + g_idx[row]] = 1.0f;
}

extern "C" void kernel_launch(void* const* d_in, const int* in_sizes, int n_in,
                              void* d_out, int out_size)
{
    const float* hid = (const float*)d_in[0];   // [8, 4096, 1024] fp32
    const float* w   = (const float*)d_in[1];   // [1024, 8] fp32
    float* out = (float*)d_out;

    gate_zf_kernel<<<GATE_BLOCKS + ZF_BLOCKS_A, 256>>>(hid, w, out);
    topk_zf_kernel<<<NPAIR + ZF_BLOCKS_B, 1024>>>(out);
    onehot_kernel<<<NPAIR * CAP / 512, 512>>>(out);
}

// round 14
// speedup vs baseline: 1.4967x; 1.4967x over previous
#include <cuda_runtime.h>
#include <cuda_bf16.h>
#include <stdint.h>

// Problem constants
#define BSZ 8
#define SEQ 4096
#define HID 1024
#define NEXP 8
#define CAP 512
#define NTOK (BSZ * SEQ)           // 32768
#define NPAIR (BSZ * NEXP)         // 64
#define IDX_OFF 0
#define SCORE_OFF (NPAIR * CAP)    // 32768
#define MASK_OFF (2 * NPAIR * CAP) // 65536
#define MASK_FLOATS (NPAIR * CAP * SEQ)   // 134217728

#define GATE_BLOCKS 1024           // 8 warps x 4 tokens = 32 tokens/block
#define ZF_PER_BLK  32768          // floats per zero-fill block (128 KB)
#define ZF_BLOCKS_TOTAL (MASK_FLOATS / ZF_PER_BLK)   // 4096
#define ZF_BLOCKS_A 3584           // 448 MB rides with the gate (proven shape)
#define ZF_BLOCKS_B1 (ZF_BLOCKS_TOTAL - ZF_BLOCKS_A) // 512 (64 MB) with chunk sort
#define ZF_A_FLOATS ((size_t)ZF_BLOCKS_A * ZF_PER_BLK)

#define NCHUNK 8                   // 4096 = 8 chunks of 512
#define CHUNK 512

// Scratch (device globals; no allocation allowed)
__device__ float g_aff[NPAIR * SEQ];                 // affinity [b*8+e][s]
__device__ unsigned long long g_keys[NPAIR * SEQ];   // chunk-sorted keys

// ---------------------------------------------------------------------------
// Kernel A: gate (blocks [0,1024)) + mask zero-fill (blocks [1024,+3584)).
// Gate arithmetic FROZEN bit-exact since R9 (k = 4L+j+128i partition, xor
// tree, exact max, fsub.rn, libdevice expf, sequential e-sum, __fdiv_rn).
// ---------------------------------------------------------------------------
__global__ __launch_bounds__(256) void gate_zf_kernel(
    const float* __restrict__ hid, const float* __restrict__ w,
    float* __restrict__ out)
{
    __shared__ float ws[NEXP * HID];
    int tid = threadIdx.x;

    if (blockIdx.x >= GATE_BLOCKS) {
        size_t base = (size_t)MASK_OFF +
                      (size_t)(blockIdx.x - GATE_BLOCKS) * ZF_PER_BLK;
        float4* dst = (float4*)(out + base);
        float4 z = make_float4(0.f, 0.f, 0.f, 0.f);
#pragma unroll
        for (int q = tid; q < ZF_PER_BLK / 4; q += 256)
            dst[q] = z;
        return;
    }

    // ---- gate path (bit-exact, frozen) ----
    for (int i = tid; i < HID * NEXP; i += 256) {
        int k = i >> 3, e = i & 7;
        ws[e * HID + k] = w[i];
    }
    __syncthreads();

    int warp = tid >> 5, lane = tid & 31;
    int tok0 = (blockIdx.x * 8 + warp) * 4;

    float acc[4][8];
#pragma unroll
    for (int t = 0; t < 4; t++)
#pragma unroll
        for (int e = 0; e < 8; e++) acc[t][e] = 0.0f;

    const float* h0 = hid + (size_t)tok0 * HID;

#pragma unroll
    for (int i = 0; i < 8; i++) {
        int kbase = i * 128 + lane * 4;
        float wreg[8][4];
#pragma unroll
        for (int e = 0; e < 8; e++)
#pragma unroll
            for (int j = 0; j < 4; j++)
                wreg[e][j] = ws[e * HID + kbase + j];
#pragma unroll
        for (int t = 0; t < 4; t++) {
            float4 h4 = *(const float4*)(h0 + (size_t)t * HID + kbase);
            float hj[4] = {h4.x, h4.y, h4.z, h4.w};
#pragma unroll
            for (int e = 0; e < 8; e++) {
#pragma unroll
                for (int j = 0; j < 4; j++)
                    acc[t][e] = __fmaf_rn(hj[j], wreg[e][j], acc[t][e]);
            }
        }
    }

#pragma unroll
    for (int off = 16; off > 0; off >>= 1) {
#pragma unroll
        for (int t = 0; t < 4; t++)
#pragma unroll
            for (int e = 0; e < 8; e++)
                acc[t][e] = __fadd_rn(acc[t][e],
                                      __shfl_xor_sync(0xFFFFFFFFu, acc[t][e], off));
    }

    if (lane < 4) {
        int tok = tok0 + lane;
        int b = tok >> 12;
        int s = tok & (SEQ - 1);

        float m = acc[lane][0];
#pragma unroll
        for (int e = 1; e < 8; e++) m = fmaxf(m, acc[lane][e]);

        float ex[8];
        float sum = 0.0f;
#pragma unroll
        for (int e = 0; e < 8; e++) {
            float d = __fsub_rn(acc[lane][e], m);
            ex[e] = expf(d);
            sum = __fadd_rn(sum, ex[e]);
        }
#pragma unroll
        for (int e = 0; e < 8; e++)
            g_aff[((size_t)(b * NEXP + e)) * SEQ + s] = __fdiv_rn(ex[e], sum);
    }
}

// ---------------------------------------------------------------------------
// Kernel B1: per-(pair, chunk) bitonic stages k = 2..512 (all intra-chunk;
// direction bit (i & k) uses the GLOBAL index so the result is exactly the
// state of the full 4096 network after k=512). Blocks [512, +512) stream the
// remaining 64 MB of mask zeros (proven 256-thread flat shape).
// ---------------------------------------------------------------------------
__global__ __launch_bounds__(256) void chunksort_zf_kernel(float* __restrict__ out)
{
    __shared__ unsigned long long keys[CHUNK];

    if (blockIdx.x >= NPAIR * NCHUNK) {
        size_t base = (size_t)MASK_OFF + ZF_A_FLOATS +
                      (size_t)(blockIdx.x - NPAIR * NCHUNK) * ZF_PER_BLK;
        float4* dst = (float4*)(out + base);
        float4 z = make_float4(0.f, 0.f, 0.f, 0.f);
#pragma unroll
        for (int q = threadIdx.x; q < ZF_PER_BLK / 4; q += 256)
            dst[q] = z;
        return;
    }

    int pair  = blockIdx.x >> 3;
    int chunk = blockIdx.x & 7;
    int gbase = chunk * CHUNK;                 // global index base of chunk
    const float* a = g_aff + (size_t)pair * SEQ + gbase;

    for (int t = threadIdx.x; t < CHUNK; t += 256) {
        unsigned int fb = __float_as_uint(a[t]);
        keys[t] = ((unsigned long long)fb << 32) | (unsigned int)(~(gbase + t));
    }
    __syncthreads();

    for (int k = 2; k <= CHUNK; k <<= 1) {
        for (int j = k >> 1; j > 0; j >>= 1) {
            // compare-slot indexing: 256 slots, 1 per thread
            int c = threadIdx.x;
            int t = ((c & ~(j - 1)) << 1) | (c & (j - 1));
            int txj = t | j;
            unsigned long long x = keys[t], y = keys[txj];
            bool desc = (((gbase + t) & k) == 0);
            if (desc ? (x < y) : (x > y)) { keys[t] = y; keys[txj] = x; }
            __syncthreads();
        }
    }

    unsigned long long* dst = g_keys + (size_t)pair * SEQ + gbase;
    for (int t = threadIdx.x; t < CHUNK; t += 256)
        dst[t] = keys[t];
}

// ---------------------------------------------------------------------------
// Kernel B2: cross-chunk merge stages k = 1024, 2048, 4096 (33 stages) per
// pair, then fused epilogue: indices, scores, one-hot scatter.
// ---------------------------------------------------------------------------
__global__ __launch_bounds__(1024) void merge_epi_kernel(float* __restrict__ out)
{
    __shared__ unsigned long long keys[SEQ];
    int pair = blockIdx.x;
    const unsigned long long* src = g_keys + (size_t)pair * SEQ;

    for (int t = threadIdx.x; t < SEQ; t += 1024)
        keys[t] = src[t];
    __syncthreads();

    for (int k = 1024; k <= SEQ; k <<= 1) {
        for (int j = k >> 1; j > 0; j >>= 1) {
#pragma unroll 2
            for (int c = threadIdx.x; c < SEQ / 2; c += 1024) {
                int t = ((c & ~(j - 1)) << 1) | (c & (j - 1));
                int txj = t | j;
                unsigned long long x = keys[t], y = keys[txj];
                bool desc = ((t & k) == 0);
                if (desc ? (x < y) : (x > y)) { keys[t] = y; keys[txj] = x; }
            }
            __syncthreads();
        }
    }

    int cslot = threadIdx.x;
    if (cslot < CAP) {
        unsigned long long key = keys[cslot];
        int   si = (int)(~(unsigned int)key);
        float v  = __uint_as_float((unsigned int)(key >> 32));
        int row = pair * CAP + cslot;
        out[IDX_OFF + row]   = (float)si;                 // topk_indices
        out[SCORE_OFF + row] = v;                         // topk_scores
        out[MASK_OFF + (size_t)row * SEQ + si] = 1.0f;    // one-hot
    }
}

extern "C" void kernel_launch(void* const* d_in, const int* in_sizes, int n_in,
                              void* d_out, int out_size)
{
    const float* hid = (const float*)d_in[0];   // [8, 4096, 1024] fp32
    const float* w   = (const float*)d_in[1];   // [1024, 8] fp32
    float* out = (float*)d_out;

    gate_zf_kernel<<<GATE_BLOCKS + ZF_BLOCKS_A, 256>>>(hid, w, out);
    chunksort_zf_kernel<<<NPAIR * NCHUNK + ZF_BLOCKS_B1, 256>>>(out);
    merge_epi_kernel<<<NPAIR, 1024>>>(out);
}